// round 2
// baseline (speedup 1.0000x reference)
#include <cuda_runtime.h>

#define NN 100000
#define NE 1600000
#define F0 256
#define F1 128
#define F2 64
#define EPSV 1e-5f

// ---------------- scratch (device globals; no allocations allowed) ----------------
__device__ __align__(16) float g_h1s [NN * F1];   // (x @ W1) * dinv[row]
__device__ __align__(16) float g_hbn1[NN * F1];   // BN+ReLU(agg1)
__device__ __align__(16) float g_h2s [NN * F2];   // (hbn1 @ W2) * dinv[row]
__device__ __align__(16) float g_hbn2[NN * F2];   // BN+ReLU(agg2)
__device__ float g_dinv[NN];
__device__ int   g_cnt [NN];
__device__ int   g_ptr [NN + 1];
__device__ int   g_cursor[NN];
__device__ int   g_srcs[NE];

// ---------------- CSR build ----------------
__global__ void k_zero_cnt() {
    int i = blockIdx.x * blockDim.x + threadIdx.x;
    if (i < NN) g_cnt[i] = 0;
}

__global__ void k_hist(const int* __restrict__ col) {
    int e = blockIdx.x * blockDim.x + threadIdx.x;
    if (e < NE) atomicAdd(&g_cnt[col[e]], 1);
}

// Single-block exclusive scan over 100k counts; also emits dinv = rsqrt(deg+1)
__global__ void k_scan() {
    __shared__ int sh[1024];
    const int t = threadIdx.x;
    const int CH = (NN + 1023) / 1024;  // 98
    int start = t * CH;
    int end = start + CH; if (end > NN) end = NN;
    if (start > NN) start = NN;
    int ls = 0;
    for (int i = start; i < end; i++) ls += g_cnt[i];
    sh[t] = ls;
    __syncthreads();
    for (int off = 1; off < 1024; off <<= 1) {
        int v = (t >= off) ? sh[t - off] : 0;
        __syncthreads();
        sh[t] += v;
        __syncthreads();
    }
    int run = sh[t] - ls;  // exclusive prefix
    for (int i = start; i < end; i++) {
        g_ptr[i] = run;
        g_cursor[i] = run;
        run += g_cnt[i];
        g_dinv[i] = rsqrtf((float)(g_cnt[i] + 1));  // +1 self-loop
    }
    if (t == 1023) g_ptr[NN] = sh[1023];
}

__global__ void k_scatter(const int* __restrict__ row, const int* __restrict__ col) {
    int e = blockIdx.x * blockDim.x + threadIdx.x;
    if (e < NE) {
        int c = col[e];
        int p = atomicAdd(&g_cursor[c], 1);
        g_srcs[p] = row[e];
    }
}

// ---------------- SGEMM with per-row scale epilogue ----------------
// C[M,N] = (A[M,K] @ B[K,N]) * dinv[row]
// WHICH==0: A=arg(x),     C=g_h1s
// WHICH==1: A=g_hbn1,     C=g_h2s
template <int BM, int BN, int WHICH>
__global__ __launch_bounds__((BM / 8) * (BN / 8))
void sgemm_rowscale(const float* __restrict__ Aarg, const float* __restrict__ Bmat,
                    int M, int N, int K) {
    constexpr int BK = 8, TM = 8, TN = 8;
    constexpr int THREADS = (BM / TM) * (BN / TN);
    const float* __restrict__ A = (WHICH == 0) ? Aarg : g_hbn1;
    float* __restrict__ C = (WHICH == 0) ? g_h1s : g_h2s;

    __shared__ float As[BK][BM];
    __shared__ float Bs[BK][BN];

    const int tid = threadIdx.x;
    const int tcol = tid % (BN / TN);
    const int trow = tid / (BN / TN);
    const int rowBase = blockIdx.y * BM;
    const int colBase = blockIdx.x * BN;

    float acc[TM][TN];
#pragma unroll
    for (int m = 0; m < TM; m++)
#pragma unroll
        for (int n = 0; n < TN; n++) acc[m][n] = 0.f;

    for (int kt = 0; kt < K; kt += BK) {
        // load A tile (BM x BK), transposed into As
#pragma unroll
        for (int i = tid; i < BM * BK / 4; i += THREADS) {
            int r = i / (BK / 4);
            int cv = i % (BK / 4);
            int gr = rowBase + r;
            float4 v = make_float4(0.f, 0.f, 0.f, 0.f);
            if (gr < M)
                v = *reinterpret_cast<const float4*>(&A[(size_t)gr * K + kt + cv * 4]);
            As[cv * 4 + 0][r] = v.x;
            As[cv * 4 + 1][r] = v.y;
            As[cv * 4 + 2][r] = v.z;
            As[cv * 4 + 3][r] = v.w;
        }
        // load B tile (BK x BN)
#pragma unroll
        for (int i = tid; i < BK * BN / 4; i += THREADS) {
            int r = i / (BN / 4);
            int cv = i % (BN / 4);
            float4 v = *reinterpret_cast<const float4*>(
                &Bmat[(size_t)(kt + r) * N + colBase + cv * 4]);
            *reinterpret_cast<float4*>(&Bs[r][cv * 4]) = v;
        }
        __syncthreads();
#pragma unroll
        for (int k = 0; k < BK; k++) {
            float ra[TM], rb[TN];
#pragma unroll
            for (int m = 0; m < TM; m++) ra[m] = As[k][trow * TM + m];
#pragma unroll
            for (int n = 0; n < TN; n++) rb[n] = Bs[k][tcol * TN + n];
#pragma unroll
            for (int m = 0; m < TM; m++)
#pragma unroll
                for (int n = 0; n < TN; n++) acc[m][n] = fmaf(ra[m], rb[n], acc[m][n]);
        }
        __syncthreads();
    }

#pragma unroll
    for (int m = 0; m < TM; m++) {
        int gr = rowBase + trow * TM + m;
        if (gr < M) {
            float s = g_dinv[gr];
#pragma unroll
            for (int n = 0; n < TN; n += 4) {
                float4 v;
                v.x = acc[m][n + 0] * s;
                v.y = acc[m][n + 1] * s;
                v.z = acc[m][n + 2] * s;
                v.w = acc[m][n + 3] * s;
                *reinterpret_cast<float4*>(
                    &C[(size_t)gr * N + colBase + tcol * TN + n]) = v;
            }
        }
    }
}

// ---------------- fused aggregation + bias + BN + ReLU ----------------
__device__ __forceinline__ float bnrelu(float x, float b, float m, float v, float g, float be) {
    float t = (x + b - m) * rsqrtf(v + EPSV) * g + be;
    return t > 0.f ? t : 0.f;
}

// layer 1: 128 features, float4 per lane
__global__ void k_agg1(const float* __restrict__ pb, const float* __restrict__ pm,
                       const float* __restrict__ pv, const float* __restrict__ pg,
                       const float* __restrict__ pbe) {
    int gw = (blockIdx.x * blockDim.x + threadIdx.x) >> 5;
    int lane = threadIdx.x & 31;
    if (gw >= NN) return;
    const float4* __restrict__ h4 = reinterpret_cast<const float4*>(g_h1s);
    int s = g_ptr[gw], e = g_ptr[gw + 1];
    float4 acc = __ldg(&h4[(size_t)gw * 32 + lane]);  // self-loop: h1s[v] = h1[v]*dinv[v]
    int i = s;
    for (; i + 3 < e; i += 4) {
        int r0 = g_srcs[i], r1 = g_srcs[i + 1], r2 = g_srcs[i + 2], r3 = g_srcs[i + 3];
        float4 a = __ldg(&h4[(size_t)r0 * 32 + lane]);
        float4 b = __ldg(&h4[(size_t)r1 * 32 + lane]);
        float4 c = __ldg(&h4[(size_t)r2 * 32 + lane]);
        float4 d = __ldg(&h4[(size_t)r3 * 32 + lane]);
        acc.x += a.x + b.x + c.x + d.x;
        acc.y += a.y + b.y + c.y + d.y;
        acc.z += a.z + b.z + c.z + d.z;
        acc.w += a.w + b.w + c.w + d.w;
    }
    for (; i < e; i++) {
        int r = g_srcs[i];
        float4 a = __ldg(&h4[(size_t)r * 32 + lane]);
        acc.x += a.x; acc.y += a.y; acc.z += a.z; acc.w += a.w;
    }
    float dv = g_dinv[gw];
    acc.x *= dv; acc.y *= dv; acc.z *= dv; acc.w *= dv;
    float4 B = reinterpret_cast<const float4*>(pb)[lane];
    float4 M = reinterpret_cast<const float4*>(pm)[lane];
    float4 V = reinterpret_cast<const float4*>(pv)[lane];
    float4 G = reinterpret_cast<const float4*>(pg)[lane];
    float4 E = reinterpret_cast<const float4*>(pbe)[lane];
    float4 o;
    o.x = bnrelu(acc.x, B.x, M.x, V.x, G.x, E.x);
    o.y = bnrelu(acc.y, B.y, M.y, V.y, G.y, E.y);
    o.z = bnrelu(acc.z, B.z, M.z, V.z, G.z, E.z);
    o.w = bnrelu(acc.w, B.w, M.w, V.w, G.w, E.w);
    reinterpret_cast<float4*>(g_hbn1)[(size_t)gw * 32 + lane] = o;
}

// layer 2: 64 features, float2 per lane
__global__ void k_agg2(const float* __restrict__ pb, const float* __restrict__ pm,
                       const float* __restrict__ pv, const float* __restrict__ pg,
                       const float* __restrict__ pbe) {
    int gw = (blockIdx.x * blockDim.x + threadIdx.x) >> 5;
    int lane = threadIdx.x & 31;
    if (gw >= NN) return;
    const float2* __restrict__ h2 = reinterpret_cast<const float2*>(g_h2s);
    int s = g_ptr[gw], e = g_ptr[gw + 1];
    float2 acc = __ldg(&h2[(size_t)gw * 32 + lane]);
    int i = s;
    for (; i + 3 < e; i += 4) {
        int r0 = g_srcs[i], r1 = g_srcs[i + 1], r2 = g_srcs[i + 2], r3 = g_srcs[i + 3];
        float2 a = __ldg(&h2[(size_t)r0 * 32 + lane]);
        float2 b = __ldg(&h2[(size_t)r1 * 32 + lane]);
        float2 c = __ldg(&h2[(size_t)r2 * 32 + lane]);
        float2 d = __ldg(&h2[(size_t)r3 * 32 + lane]);
        acc.x += a.x + b.x + c.x + d.x;
        acc.y += a.y + b.y + c.y + d.y;
    }
    for (; i < e; i++) {
        int r = g_srcs[i];
        float2 a = __ldg(&h2[(size_t)r * 32 + lane]);
        acc.x += a.x; acc.y += a.y;
    }
    float dv = g_dinv[gw];
    acc.x *= dv; acc.y *= dv;
    float2 B = reinterpret_cast<const float2*>(pb)[lane];
    float2 M = reinterpret_cast<const float2*>(pm)[lane];
    float2 V = reinterpret_cast<const float2*>(pv)[lane];
    float2 G = reinterpret_cast<const float2*>(pg)[lane];
    float2 E = reinterpret_cast<const float2*>(pbe)[lane];
    float2 o;
    o.x = bnrelu(acc.x, B.x, M.x, V.x, G.x, E.x);
    o.y = bnrelu(acc.y, B.y, M.y, V.y, G.y, E.y);
    reinterpret_cast<float2*>(g_hbn2)[(size_t)gw * 32 + lane] = o;
}

// ---------------- final linear 64 -> 2 ----------------
__global__ void k_final(const float* __restrict__ fcW, const float* __restrict__ fcb,
                        float* __restrict__ out) {
    int gw = (blockIdx.x * blockDim.x + threadIdx.x) >> 5;
    int lane = threadIdx.x & 31;
    if (gw >= NN) return;
    float2 hv = reinterpret_cast<const float2*>(g_hbn2)[(size_t)gw * 32 + lane];
    // fcW row-major [64][2]; w4[lane] = {W[2l][0], W[2l][1], W[2l+1][0], W[2l+1][1]}
    float4 w = reinterpret_cast<const float4*>(fcW)[lane];
    float a0 = hv.x * w.x + hv.y * w.z;
    float a1 = hv.x * w.y + hv.y * w.w;
#pragma unroll
    for (int off = 16; off; off >>= 1) {
        a0 += __shfl_down_sync(0xffffffffu, a0, off);
        a1 += __shfl_down_sync(0xffffffffu, a1, off);
    }
    if (lane == 0) {
        out[(size_t)gw * 2 + 0] = a0 + fcb[0];
        out[(size_t)gw * 2 + 1] = a1 + fcb[1];
    }
}

// ---------------- launch ----------------
extern "C" void kernel_launch(void* const* d_in, const int* in_sizes, int n_in,
                              void* d_out, int out_size) {
    const float* x   = (const float*)d_in[0];
    const int*   ei  = (const int*)d_in[1];
    const int*   row = ei;
    const int*   col = ei + NE;
    const float* W1  = (const float*)d_in[2];
    const float* b1  = (const float*)d_in[3];
    const float* g1  = (const float*)d_in[4];
    const float* be1 = (const float*)d_in[5];
    const float* m1  = (const float*)d_in[6];
    const float* v1  = (const float*)d_in[7];
    const float* W2  = (const float*)d_in[8];
    const float* b2  = (const float*)d_in[9];
    const float* g2  = (const float*)d_in[10];
    const float* be2 = (const float*)d_in[11];
    const float* m2  = (const float*)d_in[12];
    const float* v2  = (const float*)d_in[13];
    const float* fcW = (const float*)d_in[14];
    const float* fcb = (const float*)d_in[15];
    float* out = (float*)d_out;

    // CSR build (counting sort by dst)
    k_zero_cnt<<<(NN + 255) / 256, 256>>>();
    k_hist<<<(NE + 255) / 256, 256>>>(col);
    k_scan<<<1, 1024>>>();
    k_scatter<<<(NE + 255) / 256, 256>>>(row, col);

    // layer 1
    sgemm_rowscale<128, 128, 0><<<dim3(F1 / 128, (NN + 127) / 128), 256>>>(x, W1, NN, F1, F0);
    k_agg1<<<(NN * 32 + 255) / 256, 256>>>(b1, m1, v1, g1, be1);

    // layer 2
    sgemm_rowscale<128, 64, 1><<<dim3(F2 / 64, (NN + 127) / 128), 128>>>(nullptr, W2, NN, F2, F1);
    k_agg2<<<(NN * 32 + 255) / 256, 256>>>(b2, m2, v2, g2, be2);

    // final linear
    k_final<<<(NN * 32 + 255) / 256, 256>>>(fcW, fcb, out);
}

// round 6
// speedup vs baseline: 1.8370x; 1.8370x over previous
#include <cuda_runtime.h>
#include <cstdint>

#define NN 100000
#define NE 1600000
#define F0 256
#define F1 128
#define F2 64
#define EPSV 1e-5f

// ---------------- scratch (device globals; no allocations allowed) ----------------
__device__ __align__(16) float g_h1s [NN * F1];   // (x @ W1) * dinv[row]
__device__ __align__(16) float g_hbn1[NN * F1];   // BN+ReLU(agg1)
__device__ __align__(16) float g_h2s [NN * F2];   // (hbn1 @ W2) * dinv[row]
__device__ __align__(16) float g_hbn2[NN * F2];   // BN+ReLU(agg2)
__device__ float g_dinv[NN];
__device__ int   g_cnt [NN];
__device__ int   g_ptr [NN + 1];
__device__ int   g_cursor[NN];
__device__ int   g_srcs[NE];
__device__ int   g_bsum[128];

// ---------------- CSR build ----------------
__global__ void k_zero_cnt() {
    int i = blockIdx.x * blockDim.x + threadIdx.x;
    if (i < NN) g_cnt[i] = 0;
}

__global__ void k_hist(const int* __restrict__ col) {
    int e = blockIdx.x * blockDim.x + threadIdx.x;
    if (e < NE) atomicAdd(&g_cnt[col[e]], 1);
}

// multi-block scan: pass 1 (block-local scan + block sums + dinv)
__global__ void k_scan1() {
    __shared__ int sh[1024];
    int b = blockIdx.x, t = threadIdx.x;
    int i = b * 1024 + t;
    int c = (i < NN) ? g_cnt[i] : 0;
    sh[t] = c;
    __syncthreads();
    for (int off = 1; off < 1024; off <<= 1) {
        int v = (t >= off) ? sh[t - off] : 0;
        __syncthreads();
        sh[t] += v;
        __syncthreads();
    }
    if (i < NN) {
        g_ptr[i] = sh[t] - c;  // block-local exclusive
        g_dinv[i] = rsqrtf((float)(c + 1));
    }
    if (t == 1023) g_bsum[b] = sh[1023];
}

// pass 2: exclusive scan of block sums
__global__ void k_scan2() {
    __shared__ int sh[128];
    const int NB = (NN + 1023) / 1024;  // 98
    int t = threadIdx.x;
    int v = (t < NB) ? g_bsum[t] : 0;
    sh[t] = v;
    __syncthreads();
    for (int off = 1; off < 128; off <<= 1) {
        int u = (t >= off) ? sh[t - off] : 0;
        __syncthreads();
        sh[t] += u;
        __syncthreads();
    }
    if (t < NB) g_bsum[t] = sh[t] - v;  // exclusive
}

// pass 3: add block offsets, init cursors
__global__ void k_scan3() {
    int b = blockIdx.x, t = threadIdx.x;
    int i = b * 1024 + t;
    if (i < NN) {
        int p = g_ptr[i] + g_bsum[b];
        g_ptr[i] = p;
        g_cursor[i] = p;
    }
    if (i == 0) g_ptr[NN] = NE;
}

__global__ void k_scatter(const int* __restrict__ row, const int* __restrict__ col) {
    int e = blockIdx.x * blockDim.x + threadIdx.x;
    if (e < NE) {
        int c = col[e];
        int p = atomicAdd(&g_cursor[c], 1);
        g_srcs[p] = row[e];
    }
}

// ================= tf32 mma.sync helpers (baseline PTX, sm_80+) =================
__device__ __forceinline__ void split_tf32(float a, float& hi, float& lo) {
    uint32_t hb;
    asm("cvt.rna.tf32.f32 %0, %1;" : "=r"(hb) : "f"(a));
    hi = __uint_as_float(hb);
    float r = a - hi;
    uint32_t lb;
    asm("cvt.rna.tf32.f32 %0, %1;" : "=r"(lb) : "f"(r));
    lo = __uint_as_float(lb);
}

__device__ __forceinline__ void mma1688(float* c, const float* a, const float* b) {
    asm volatile(
        "mma.sync.aligned.m16n8k8.row.col.f32.tf32.tf32.f32 "
        "{%0,%1,%2,%3}, {%4,%5,%6,%7}, {%8,%9}, {%0,%1,%2,%3};"
        : "+f"(c[0]), "+f"(c[1]), "+f"(c[2]), "+f"(c[3])
        : "r"(__float_as_uint(a[0])), "r"(__float_as_uint(a[1])),
          "r"(__float_as_uint(a[2])), "r"(__float_as_uint(a[3])),
          "r"(__float_as_uint(b[0])), "r"(__float_as_uint(b[1])));
}

// ================= 3xTF32 tensor-core GEMM with rowscale epilogue =================
// C[M,NT] = (A[M,KK] @ B[KK,NT]) * dinv[row]
// WHICH==0: A=arg(x), C=g_h1s ; WHICH==1: A=g_hbn1, C=g_h2s
// CTA tile: 128 x NT; 8 warps in 4(m) x 2(n); warp tile 32 x NT/2; BK=16.
template <int NT, int KK, int WHICH>
__global__ void __launch_bounds__(256)
mma_gemm(const float* __restrict__ Aarg, const float* __restrict__ Bmat) {
    const float* __restrict__ A = (WHICH == 0) ? Aarg : g_hbn1;
    float* __restrict__ C = (WHICH == 0) ? g_h1s : g_h2s;

    constexpr int BK = 16;
    constexpr int SA = BK + 4;        // A smem stride (20): frag banks 20g+t -> all 32
    constexpr int SB = NT + 8;        // B smem stride: frag banks 8t+g -> all 32
    constexpr int WN = NT / 2;        // warp n-width (64 or 32)
    constexpr int MSUB = 2;           // 2 x m16 = 32 rows per warp
    constexpr int NSUB = WN / 8;      // 8 or 4 n-subtiles

    __shared__ float As_hi[128 * SA], As_lo[128 * SA];
    __shared__ float Bs_hi[BK * SB],  Bs_lo[BK * SB];

    const int tid = threadIdx.x, wid = tid >> 5, lane = tid & 31;
    const int g = lane >> 2, t = lane & 3;
    const int warp_m = wid & 3, warp_n = wid >> 2;
    const int rowBase = blockIdx.x * 128;

    float acc[MSUB][NSUB][4];
#pragma unroll
    for (int i = 0; i < MSUB; i++)
#pragma unroll
        for (int j = 0; j < NSUB; j++)
#pragma unroll
            for (int q = 0; q < 4; q++) acc[i][j][q] = 0.f;

    for (int kt = 0; kt < KK; kt += BK) {
        // ---- A tile: 128 x 16, split hi/lo ----
#pragma unroll
        for (int it = 0; it < 2; it++) {
            int idx = tid + it * 256;     // 512 float4 slots
            int r = idx >> 2, v = idx & 3;
            int gr = rowBase + r;
            float4 val = make_float4(0.f, 0.f, 0.f, 0.f);
            if (gr < NN)
                val = *reinterpret_cast<const float4*>(&A[(size_t)gr * KK + kt + v * 4]);
            float4 hi, lo;
            split_tf32(val.x, hi.x, lo.x);
            split_tf32(val.y, hi.y, lo.y);
            split_tf32(val.z, hi.z, lo.z);
            split_tf32(val.w, hi.w, lo.w);
            *reinterpret_cast<float4*>(&As_hi[r * SA + v * 4]) = hi;
            *reinterpret_cast<float4*>(&As_lo[r * SA + v * 4]) = lo;
        }
        // ---- B tile: 16 x NT, split hi/lo ----
#pragma unroll
        for (int it = 0; it < (BK * NT / 4) / 256; it++) {
            int idx = tid + it * 256;
            int r = idx / (NT / 4), v = idx % (NT / 4);
            float4 val = *reinterpret_cast<const float4*>(&Bmat[(size_t)(kt + r) * NT + v * 4]);
            float4 hi, lo;
            split_tf32(val.x, hi.x, lo.x);
            split_tf32(val.y, hi.y, lo.y);
            split_tf32(val.z, hi.z, lo.z);
            split_tf32(val.w, hi.w, lo.w);
            *reinterpret_cast<float4*>(&Bs_hi[r * SB + v * 4]) = hi;
            *reinterpret_cast<float4*>(&Bs_lo[r * SB + v * 4]) = lo;
        }
        __syncthreads();

#pragma unroll
        for (int ks = 0; ks < BK / 8; ks++) {
            const int k0 = ks * 8;
            // B fragments for all n-subtiles
            float bh[NSUB][2], blo[NSUB][2];
#pragma unroll
            for (int sn = 0; sn < NSUB; sn++) {
                int col = warp_n * WN + sn * 8 + g;
                bh[sn][0]  = Bs_hi[(k0 + t) * SB + col];
                bh[sn][1]  = Bs_hi[(k0 + t + 4) * SB + col];
                blo[sn][0] = Bs_lo[(k0 + t) * SB + col];
                blo[sn][1] = Bs_lo[(k0 + t + 4) * SB + col];
            }
#pragma unroll
            for (int sm = 0; sm < MSUB; sm++) {
                int rb = warp_m * 32 + sm * 16;
                float ah[4], alo[4];
                ah[0]  = As_hi[(rb + g) * SA + k0 + t];
                ah[1]  = As_hi[(rb + g + 8) * SA + k0 + t];
                ah[2]  = As_hi[(rb + g) * SA + k0 + t + 4];
                ah[3]  = As_hi[(rb + g + 8) * SA + k0 + t + 4];
                alo[0] = As_lo[(rb + g) * SA + k0 + t];
                alo[1] = As_lo[(rb + g + 8) * SA + k0 + t];
                alo[2] = As_lo[(rb + g) * SA + k0 + t + 4];
                alo[3] = As_lo[(rb + g + 8) * SA + k0 + t + 4];
#pragma unroll
                for (int sn = 0; sn < NSUB; sn++) {
                    mma1688(acc[sm][sn], ah, bh[sn]);    // hi*hi
                    mma1688(acc[sm][sn], ah, blo[sn]);   // hi*lo
                    mma1688(acc[sm][sn], alo, bh[sn]);   // lo*hi
                }
            }
        }
        __syncthreads();
    }

    // ---- epilogue: scale by dinv[row], store ----
#pragma unroll
    for (int sm = 0; sm < MSUB; sm++) {
        int gr0 = rowBase + warp_m * 32 + sm * 16 + g;
        int gr1 = gr0 + 8;
        float dv0 = (gr0 < NN) ? g_dinv[gr0] : 0.f;
        float dv1 = (gr1 < NN) ? g_dinv[gr1] : 0.f;
#pragma unroll
        for (int sn = 0; sn < NSUB; sn++) {
            int col = warp_n * WN + sn * 8 + t * 2;
            if (gr0 < NN) {
                float2 o0 = make_float2(acc[sm][sn][0] * dv0, acc[sm][sn][1] * dv0);
                *reinterpret_cast<float2*>(&C[(size_t)gr0 * NT + col]) = o0;
            }
            if (gr1 < NN) {
                float2 o1 = make_float2(acc[sm][sn][2] * dv1, acc[sm][sn][3] * dv1);
                *reinterpret_cast<float2*>(&C[(size_t)gr1 * NT + col]) = o1;
            }
        }
    }
}

// ---------------- fused aggregation + bias + BN + ReLU ----------------
__device__ __forceinline__ float bnrelu(float x, float b, float m, float v, float g, float be) {
    float t = (x + b - m) * rsqrtf(v + EPSV) * g + be;
    return t > 0.f ? t : 0.f;
}

// layer 1: 128 features, float4 per lane
__global__ void k_agg1(const float* __restrict__ pb, const float* __restrict__ pm,
                       const float* __restrict__ pv, const float* __restrict__ pg,
                       const float* __restrict__ pbe) {
    int gw = (blockIdx.x * blockDim.x + threadIdx.x) >> 5;
    int lane = threadIdx.x & 31;
    if (gw >= NN) return;
    const float4* __restrict__ h4 = reinterpret_cast<const float4*>(g_h1s);
    int s = g_ptr[gw], e = g_ptr[gw + 1];
    float4 acc = __ldg(&h4[(size_t)gw * 32 + lane]);  // self-loop: h1s[v] = h1[v]*dinv[v]
    int i = s;
    for (; i + 3 < e; i += 4) {
        int r0 = g_srcs[i], r1 = g_srcs[i + 1], r2 = g_srcs[i + 2], r3 = g_srcs[i + 3];
        float4 a = __ldg(&h4[(size_t)r0 * 32 + lane]);
        float4 b = __ldg(&h4[(size_t)r1 * 32 + lane]);
        float4 c = __ldg(&h4[(size_t)r2 * 32 + lane]);
        float4 d = __ldg(&h4[(size_t)r3 * 32 + lane]);
        acc.x += a.x + b.x + c.x + d.x;
        acc.y += a.y + b.y + c.y + d.y;
        acc.z += a.z + b.z + c.z + d.z;
        acc.w += a.w + b.w + c.w + d.w;
    }
    for (; i < e; i++) {
        int r = g_srcs[i];
        float4 a = __ldg(&h4[(size_t)r * 32 + lane]);
        acc.x += a.x; acc.y += a.y; acc.z += a.z; acc.w += a.w;
    }
    float dv = g_dinv[gw];
    acc.x *= dv; acc.y *= dv; acc.z *= dv; acc.w *= dv;
    float4 B = reinterpret_cast<const float4*>(pb)[lane];
    float4 M = reinterpret_cast<const float4*>(pm)[lane];
    float4 V = reinterpret_cast<const float4*>(pv)[lane];
    float4 G = reinterpret_cast<const float4*>(pg)[lane];
    float4 E = reinterpret_cast<const float4*>(pbe)[lane];
    float4 o;
    o.x = bnrelu(acc.x, B.x, M.x, V.x, G.x, E.x);
    o.y = bnrelu(acc.y, B.y, M.y, V.y, G.y, E.y);
    o.z = bnrelu(acc.z, B.z, M.z, V.z, G.z, E.z);
    o.w = bnrelu(acc.w, B.w, M.w, V.w, G.w, E.w);
    reinterpret_cast<float4*>(g_hbn1)[(size_t)gw * 32 + lane] = o;
}

// layer 2: 64 features, float2 per lane
__global__ void k_agg2(const float* __restrict__ pb, const float* __restrict__ pm,
                       const float* __restrict__ pv, const float* __restrict__ pg,
                       const float* __restrict__ pbe) {
    int gw = (blockIdx.x * blockDim.x + threadIdx.x) >> 5;
    int lane = threadIdx.x & 31;
    if (gw >= NN) return;
    const float2* __restrict__ h2 = reinterpret_cast<const float2*>(g_h2s);
    int s = g_ptr[gw], e = g_ptr[gw + 1];
    float2 acc = __ldg(&h2[(size_t)gw * 32 + lane]);
    int i = s;
    for (; i + 3 < e; i += 4) {
        int r0 = g_srcs[i], r1 = g_srcs[i + 1], r2 = g_srcs[i + 2], r3 = g_srcs[i + 3];
        float2 a = __ldg(&h2[(size_t)r0 * 32 + lane]);
        float2 b = __ldg(&h2[(size_t)r1 * 32 + lane]);
        float2 c = __ldg(&h2[(size_t)r2 * 32 + lane]);
        float2 d = __ldg(&h2[(size_t)r3 * 32 + lane]);
        acc.x += a.x + b.x + c.x + d.x;
        acc.y += a.y + b.y + c.y + d.y;
    }
    for (; i < e; i++) {
        int r = g_srcs[i];
        float2 a = __ldg(&h2[(size_t)r * 32 + lane]);
        acc.x += a.x; acc.y += a.y;
    }
    float dv = g_dinv[gw];
    acc.x *= dv; acc.y *= dv;
    float2 B = reinterpret_cast<const float2*>(pb)[lane];
    float2 M = reinterpret_cast<const float2*>(pm)[lane];
    float2 V = reinterpret_cast<const float2*>(pv)[lane];
    float2 G = reinterpret_cast<const float2*>(pg)[lane];
    float2 E = reinterpret_cast<const float2*>(pbe)[lane];
    float2 o;
    o.x = bnrelu(acc.x, B.x, M.x, V.x, G.x, E.x);
    o.y = bnrelu(acc.y, B.y, M.y, V.y, G.y, E.y);
    reinterpret_cast<float2*>(g_hbn2)[(size_t)gw * 32 + lane] = o;
}

// ---------------- final linear 64 -> 2 ----------------
__global__ void k_final(const float* __restrict__ fcW, const float* __restrict__ fcb,
                        float* __restrict__ out) {
    int gw = (blockIdx.x * blockDim.x + threadIdx.x) >> 5;
    int lane = threadIdx.x & 31;
    if (gw >= NN) return;
    float2 hv = reinterpret_cast<const float2*>(g_hbn2)[(size_t)gw * 32 + lane];
    float4 w = reinterpret_cast<const float4*>(fcW)[lane];
    float a0 = hv.x * w.x + hv.y * w.z;
    float a1 = hv.x * w.y + hv.y * w.w;
#pragma unroll
    for (int off = 16; off; off >>= 1) {
        a0 += __shfl_down_sync(0xffffffffu, a0, off);
        a1 += __shfl_down_sync(0xffffffffu, a1, off);
    }
    if (lane == 0) {
        out[(size_t)gw * 2 + 0] = a0 + fcb[0];
        out[(size_t)gw * 2 + 1] = a1 + fcb[1];
    }
}

// ---------------- launch ----------------
extern "C" void kernel_launch(void* const* d_in, const int* in_sizes, int n_in,
                              void* d_out, int out_size) {
    const float* x   = (const float*)d_in[0];
    const int*   ei  = (const int*)d_in[1];
    const int*   row = ei;
    const int*   col = ei + NE;
    const float* W1  = (const float*)d_in[2];
    const float* b1  = (const float*)d_in[3];
    const float* g1  = (const float*)d_in[4];
    const float* be1 = (const float*)d_in[5];
    const float* m1  = (const float*)d_in[6];
    const float* v1  = (const float*)d_in[7];
    const float* W2  = (const float*)d_in[8];
    const float* b2  = (const float*)d_in[9];
    const float* g2  = (const float*)d_in[10];
    const float* be2 = (const float*)d_in[11];
    const float* m2  = (const float*)d_in[12];
    const float* v2  = (const float*)d_in[13];
    const float* fcW = (const float*)d_in[14];
    const float* fcb = (const float*)d_in[15];
    float* out = (float*)d_out;

    const int NB = (NN + 1023) / 1024;       // 98
    const int NTILES = (NN + 127) / 128;     // 782

    // CSR build (counting sort by dst)
    k_zero_cnt<<<(NN + 255) / 256, 256>>>();
    k_hist<<<(NE + 255) / 256, 256>>>(col);
    k_scan1<<<NB, 1024>>>();
    k_scan2<<<1, 128>>>();
    k_scan3<<<NB, 1024>>>();
    k_scatter<<<(NE + 255) / 256, 256>>>(row, col);

    // layer 1
    mma_gemm<F1, F0, 0><<<NTILES, 256>>>(x, W1);
    k_agg1<<<(NN * 32 + 255) / 256, 256>>>(b1, m1, v1, g1, be1);

    // layer 2
    mma_gemm<F2, F1, 1><<<NTILES, 256>>>(nullptr, W2);
    k_agg2<<<(NN * 32 + 255) / 256, 256>>>(b2, m2, v2, g2, be2);

    // final linear
    k_final<<<(NN * 32 + 255) / 256, 256>>>(fcW, fcb, out);
}

// round 7
// speedup vs baseline: 1.9936x; 1.0852x over previous
#include <cuda_runtime.h>
#include <cuda_fp16.h>
#include <cstdint>

#define NN 100000
#define NE 1600000
#define F0 256
#define F1 128
#define F2 64
#define EPSV 1e-5f

// ---------------- scratch (device globals; no allocations allowed) ----------------
__device__ __align__(16) __half2 g_h1s[NN * F1 / 2];  // fp16 messages: (x@W1)*dinv
__device__ __align__(16) float   g_hbn1[NN * F1];     // BN+ReLU(agg1), fp32
__device__ __align__(16) __half2 g_h2s[NN * F2 / 2];  // fp16 messages: (hbn1@W2)*dinv
__device__ float g_dinv[NN];
__device__ int   g_cnt [NN];     // zero-initialized at module load; re-zeroed in k_scan3
__device__ int   g_ptr [NN + 1];
__device__ int   g_cursor[NN];
__device__ int   g_srcs[NE];
__device__ int   g_bsum[128];

// ---------------- CSR build ----------------
__global__ void k_hist(const int* __restrict__ col) {
    int e = blockIdx.x * blockDim.x + threadIdx.x;
    if (e < NE) atomicAdd(&g_cnt[col[e]], 1);
}

// pass 1: block-local exclusive scan + block sums + dinv
__global__ void k_scan1() {
    __shared__ int sh[1024];
    int b = blockIdx.x, t = threadIdx.x;
    int i = b * 1024 + t;
    int c = (i < NN) ? g_cnt[i] : 0;
    sh[t] = c;
    __syncthreads();
    for (int off = 1; off < 1024; off <<= 1) {
        int v = (t >= off) ? sh[t - off] : 0;
        __syncthreads();
        sh[t] += v;
        __syncthreads();
    }
    if (i < NN) {
        g_ptr[i] = sh[t] - c;  // block-local exclusive
        g_dinv[i] = rsqrtf((float)(c + 1));
    }
    if (t == 1023) g_bsum[b] = sh[1023];
}

// pass 2: exclusive scan of block sums
__global__ void k_scan2() {
    __shared__ int sh[128];
    const int NB = (NN + 1023) / 1024;  // 98
    int t = threadIdx.x;
    int v = (t < NB) ? g_bsum[t] : 0;
    sh[t] = v;
    __syncthreads();
    for (int off = 1; off < 128; off <<= 1) {
        int u = (t >= off) ? sh[t - off] : 0;
        __syncthreads();
        sh[t] += u;
        __syncthreads();
    }
    if (t < NB) g_bsum[t] = sh[t] - v;  // exclusive
}

// pass 3: add block offsets, init cursors, re-zero g_cnt for the next call
__global__ void k_scan3() {
    int b = blockIdx.x, t = threadIdx.x;
    int i = b * 1024 + t;
    if (i < NN) {
        int p = g_ptr[i] + g_bsum[b];
        g_ptr[i] = p;
        g_cursor[i] = p;
        g_cnt[i] = 0;          // invariant: cnt==0 at entry of every kernel_launch
    }
    if (i == 0) g_ptr[NN] = NE;
}

__global__ void k_scatter(const int* __restrict__ row, const int* __restrict__ col) {
    int e = blockIdx.x * blockDim.x + threadIdx.x;
    if (e < NE) {
        int c = col[e];
        int p = atomicAdd(&g_cursor[c], 1);
        g_srcs[p] = row[e];
    }
}

// ================= tf32 mma.sync helpers (baseline PTX, sm_80+) =================
__device__ __forceinline__ void split_tf32(float a, float& hi, float& lo) {
    uint32_t hb;
    asm("cvt.rna.tf32.f32 %0, %1;" : "=r"(hb) : "f"(a));
    hi = __uint_as_float(hb);
    float r = a - hi;
    uint32_t lb;
    asm("cvt.rna.tf32.f32 %0, %1;" : "=r"(lb) : "f"(r));
    lo = __uint_as_float(lb);
}

__device__ __forceinline__ void mma1688(float* c, const float* a, const float* b) {
    asm volatile(
        "mma.sync.aligned.m16n8k8.row.col.f32.tf32.tf32.f32 "
        "{%0,%1,%2,%3}, {%4,%5,%6,%7}, {%8,%9}, {%0,%1,%2,%3};"
        : "+f"(c[0]), "+f"(c[1]), "+f"(c[2]), "+f"(c[3])
        : "r"(__float_as_uint(a[0])), "r"(__float_as_uint(a[1])),
          "r"(__float_as_uint(a[2])), "r"(__float_as_uint(a[3])),
          "r"(__float_as_uint(b[0])), "r"(__float_as_uint(b[1])));
}

// ================= 3xTF32 tensor-core GEMM, rowscale + fp16 store epilogue =====
// Chalf[M,NT] = half( (A[M,KK] @ B[KK,NT]) * dinv[row] )
// WHICH==0: A=arg(x), C=g_h1s ; WHICH==1: A=g_hbn1, C=g_h2s
// CTA tile: 128 x NT; 8 warps in 4(m) x 2(n); warp tile 32 x NT/2; BK=16.
template <int NT, int KK, int WHICH>
__global__ void __launch_bounds__(256)
mma_gemm(const float* __restrict__ Aarg, const float* __restrict__ Bmat) {
    const float* __restrict__ A = (WHICH == 0) ? Aarg : g_hbn1;
    __half2* __restrict__ C = (WHICH == 0) ? g_h1s : g_h2s;

    constexpr int BK = 16;
    constexpr int SA = BK + 4;        // A smem stride (20): frag banks 20g+t -> all 32
    constexpr int SB = NT + 8;        // B smem stride: frag banks 8t+g -> all 32
    constexpr int WN = NT / 2;        // warp n-width (64 or 32)
    constexpr int MSUB = 2;           // 2 x m16 = 32 rows per warp
    constexpr int NSUB = WN / 8;      // 8 or 4 n-subtiles

    __shared__ float As_hi[128 * SA], As_lo[128 * SA];
    __shared__ float Bs_hi[BK * SB],  Bs_lo[BK * SB];

    const int tid = threadIdx.x, wid = tid >> 5, lane = tid & 31;
    const int g = lane >> 2, t = lane & 3;
    const int warp_m = wid & 3, warp_n = wid >> 2;
    const int rowBase = blockIdx.x * 128;

    float acc[MSUB][NSUB][4];
#pragma unroll
    for (int i = 0; i < MSUB; i++)
#pragma unroll
        for (int j = 0; j < NSUB; j++)
#pragma unroll
            for (int q = 0; q < 4; q++) acc[i][j][q] = 0.f;

    for (int kt = 0; kt < KK; kt += BK) {
        // ---- A tile: 128 x 16, split hi/lo ----
#pragma unroll
        for (int it = 0; it < 2; it++) {
            int idx = tid + it * 256;     // 512 float4 slots
            int r = idx >> 2, v = idx & 3;
            int gr = rowBase + r;
            float4 val = make_float4(0.f, 0.f, 0.f, 0.f);
            if (gr < NN)
                val = *reinterpret_cast<const float4*>(&A[(size_t)gr * KK + kt + v * 4]);
            float4 hi, lo;
            split_tf32(val.x, hi.x, lo.x);
            split_tf32(val.y, hi.y, lo.y);
            split_tf32(val.z, hi.z, lo.z);
            split_tf32(val.w, hi.w, lo.w);
            *reinterpret_cast<float4*>(&As_hi[r * SA + v * 4]) = hi;
            *reinterpret_cast<float4*>(&As_lo[r * SA + v * 4]) = lo;
        }
        // ---- B tile: 16 x NT, split hi/lo ----
#pragma unroll
        for (int it = 0; it < (BK * NT / 4) / 256; it++) {
            int idx = tid + it * 256;
            int r = idx / (NT / 4), v = idx % (NT / 4);
            float4 val = *reinterpret_cast<const float4*>(&Bmat[(size_t)(kt + r) * NT + v * 4]);
            float4 hi, lo;
            split_tf32(val.x, hi.x, lo.x);
            split_tf32(val.y, hi.y, lo.y);
            split_tf32(val.z, hi.z, lo.z);
            split_tf32(val.w, hi.w, lo.w);
            *reinterpret_cast<float4*>(&Bs_hi[r * SB + v * 4]) = hi;
            *reinterpret_cast<float4*>(&Bs_lo[r * SB + v * 4]) = lo;
        }
        __syncthreads();

#pragma unroll
        for (int ks = 0; ks < BK / 8; ks++) {
            const int k0 = ks * 8;
            float bh[NSUB][2], blo[NSUB][2];
#pragma unroll
            for (int sn = 0; sn < NSUB; sn++) {
                int col = warp_n * WN + sn * 8 + g;
                bh[sn][0]  = Bs_hi[(k0 + t) * SB + col];
                bh[sn][1]  = Bs_hi[(k0 + t + 4) * SB + col];
                blo[sn][0] = Bs_lo[(k0 + t) * SB + col];
                blo[sn][1] = Bs_lo[(k0 + t + 4) * SB + col];
            }
#pragma unroll
            for (int sm = 0; sm < MSUB; sm++) {
                int rb = warp_m * 32 + sm * 16;
                float ah[4], alo[4];
                ah[0]  = As_hi[(rb + g) * SA + k0 + t];
                ah[1]  = As_hi[(rb + g + 8) * SA + k0 + t];
                ah[2]  = As_hi[(rb + g) * SA + k0 + t + 4];
                ah[3]  = As_hi[(rb + g + 8) * SA + k0 + t + 4];
                alo[0] = As_lo[(rb + g) * SA + k0 + t];
                alo[1] = As_lo[(rb + g + 8) * SA + k0 + t];
                alo[2] = As_lo[(rb + g) * SA + k0 + t + 4];
                alo[3] = As_lo[(rb + g + 8) * SA + k0 + t + 4];
#pragma unroll
                for (int sn = 0; sn < NSUB; sn++) {
                    mma1688(acc[sm][sn], ah, bh[sn]);    // hi*hi
                    mma1688(acc[sm][sn], ah, blo[sn]);   // hi*lo
                    mma1688(acc[sm][sn], alo, bh[sn]);   // lo*hi
                }
            }
        }
        __syncthreads();
    }

    // ---- epilogue: scale by dinv[row], convert fp16, store half2 ----
#pragma unroll
    for (int sm = 0; sm < MSUB; sm++) {
        int gr0 = rowBase + warp_m * 32 + sm * 16 + g;
        int gr1 = gr0 + 8;
        float dv0 = (gr0 < NN) ? g_dinv[gr0] : 0.f;
        float dv1 = (gr1 < NN) ? g_dinv[gr1] : 0.f;
#pragma unroll
        for (int sn = 0; sn < NSUB; sn++) {
            int col = warp_n * WN + sn * 8 + t * 2;
            if (gr0 < NN)
                C[((size_t)gr0 * NT + col) >> 1] =
                    __floats2half2_rn(acc[sm][sn][0] * dv0, acc[sm][sn][1] * dv0);
            if (gr1 < NN)
                C[((size_t)gr1 * NT + col) >> 1] =
                    __floats2half2_rn(acc[sm][sn][2] * dv1, acc[sm][sn][3] * dv1);
        }
    }
}

// ---------------- fused aggregation + bias + BN + ReLU ----------------
__device__ __forceinline__ float bnrelu(float x, float b, float m, float v, float g, float be) {
    float t = (x + b - m) * rsqrtf(v + EPSV) * g + be;
    return t > 0.f ? t : 0.f;
}

__device__ __forceinline__ float4 h2x2_to_f4(uint2 u) {
    float2 p0 = __half22float2(*reinterpret_cast<__half2*>(&u.x));
    float2 p1 = __half22float2(*reinterpret_cast<__half2*>(&u.y));
    return make_float4(p0.x, p0.y, p1.x, p1.y);
}

// layer 1: 128 fp16 features -> warp-per-node, 4 feats (8B) per lane
__global__ void k_agg1(const float* __restrict__ pb, const float* __restrict__ pm,
                       const float* __restrict__ pv, const float* __restrict__ pg,
                       const float* __restrict__ pbe) {
    int gw = (blockIdx.x * blockDim.x + threadIdx.x) >> 5;
    int lane = threadIdx.x & 31;
    if (gw >= NN) return;
    const uint2* __restrict__ h = reinterpret_cast<const uint2*>(g_h1s);  // 32 uint2/row
    int s = g_ptr[gw], e = g_ptr[gw + 1];
    float4 acc = h2x2_to_f4(__ldg(&h[(size_t)gw * 32 + lane]));  // self-loop
    int i = s;
    for (; i + 3 < e; i += 4) {
        int r0 = g_srcs[i], r1 = g_srcs[i + 1], r2 = g_srcs[i + 2], r3 = g_srcs[i + 3];
        float4 a = h2x2_to_f4(__ldg(&h[(size_t)r0 * 32 + lane]));
        float4 b = h2x2_to_f4(__ldg(&h[(size_t)r1 * 32 + lane]));
        float4 c = h2x2_to_f4(__ldg(&h[(size_t)r2 * 32 + lane]));
        float4 d = h2x2_to_f4(__ldg(&h[(size_t)r3 * 32 + lane]));
        acc.x += a.x + b.x + c.x + d.x;
        acc.y += a.y + b.y + c.y + d.y;
        acc.z += a.z + b.z + c.z + d.z;
        acc.w += a.w + b.w + c.w + d.w;
    }
    for (; i < e; i++) {
        float4 a = h2x2_to_f4(__ldg(&h[(size_t)g_srcs[i] * 32 + lane]));
        acc.x += a.x; acc.y += a.y; acc.z += a.z; acc.w += a.w;
    }
    float dv = g_dinv[gw];
    acc.x *= dv; acc.y *= dv; acc.z *= dv; acc.w *= dv;
    float4 B = reinterpret_cast<const float4*>(pb)[lane];
    float4 M = reinterpret_cast<const float4*>(pm)[lane];
    float4 V = reinterpret_cast<const float4*>(pv)[lane];
    float4 G = reinterpret_cast<const float4*>(pg)[lane];
    float4 E = reinterpret_cast<const float4*>(pbe)[lane];
    float4 o;
    o.x = bnrelu(acc.x, B.x, M.x, V.x, G.x, E.x);
    o.y = bnrelu(acc.y, B.y, M.y, V.y, G.y, E.y);
    o.z = bnrelu(acc.z, B.z, M.z, V.z, G.z, E.z);
    o.w = bnrelu(acc.w, B.w, M.w, V.w, G.w, E.w);
    reinterpret_cast<float4*>(g_hbn1)[(size_t)gw * 32 + lane] = o;
}

// layer 2: 64 fp16 features, 2 feats (4B) per lane; fused final 64->2 linear
__global__ void k_agg2_final(const float* __restrict__ pb, const float* __restrict__ pm,
                             const float* __restrict__ pv, const float* __restrict__ pg,
                             const float* __restrict__ pbe,
                             const float* __restrict__ fcW, const float* __restrict__ fcb,
                             float* __restrict__ out) {
    int gw = (blockIdx.x * blockDim.x + threadIdx.x) >> 5;
    int lane = threadIdx.x & 31;
    if (gw >= NN) return;
    const __half2* __restrict__ h = reinterpret_cast<const __half2*>(g_h2s);  // 32 half2/row
    int s = g_ptr[gw], e = g_ptr[gw + 1];
    float2 acc = __half22float2(__ldg(&h[(size_t)gw * 32 + lane]));  // self-loop
    int i = s;
    for (; i + 3 < e; i += 4) {
        int r0 = g_srcs[i], r1 = g_srcs[i + 1], r2 = g_srcs[i + 2], r3 = g_srcs[i + 3];
        float2 a = __half22float2(__ldg(&h[(size_t)r0 * 32 + lane]));
        float2 b = __half22float2(__ldg(&h[(size_t)r1 * 32 + lane]));
        float2 c = __half22float2(__ldg(&h[(size_t)r2 * 32 + lane]));
        float2 d = __half22float2(__ldg(&h[(size_t)r3 * 32 + lane]));
        acc.x += a.x + b.x + c.x + d.x;
        acc.y += a.y + b.y + c.y + d.y;
    }
    for (; i < e; i++) {
        float2 a = __half22float2(__ldg(&h[(size_t)g_srcs[i] * 32 + lane]));
        acc.x += a.x; acc.y += a.y;
    }
    float dv = g_dinv[gw];
    acc.x *= dv; acc.y *= dv;
    float2 B = reinterpret_cast<const float2*>(pb)[lane];
    float2 M = reinterpret_cast<const float2*>(pm)[lane];
    float2 V = reinterpret_cast<const float2*>(pv)[lane];
    float2 G = reinterpret_cast<const float2*>(pg)[lane];
    float2 E = reinterpret_cast<const float2*>(pbe)[lane];
    float2 o;
    o.x = bnrelu(acc.x, B.x, M.x, V.x, G.x, E.x);
    o.y = bnrelu(acc.y, B.y, M.y, V.y, G.y, E.y);
    // fused final: fcW row-major [64][2]; w = {W[2l][0],W[2l][1],W[2l+1][0],W[2l+1][1]}
    float4 w = reinterpret_cast<const float4*>(fcW)[lane];
    float a0 = o.x * w.x + o.y * w.z;
    float a1 = o.x * w.y + o.y * w.w;
#pragma unroll
    for (int off = 16; off; off >>= 1) {
        a0 += __shfl_down_sync(0xffffffffu, a0, off);
        a1 += __shfl_down_sync(0xffffffffu, a1, off);
    }
    if (lane == 0) {
        out[(size_t)gw * 2 + 0] = a0 + fcb[0];
        out[(size_t)gw * 2 + 1] = a1 + fcb[1];
    }
}

// ---------------- launch ----------------
extern "C" void kernel_launch(void* const* d_in, const int* in_sizes, int n_in,
                              void* d_out, int out_size) {
    const float* x   = (const float*)d_in[0];
    const int*   ei  = (const int*)d_in[1];
    const int*   row = ei;
    const int*   col = ei + NE;
    const float* W1  = (const float*)d_in[2];
    const float* b1  = (const float*)d_in[3];
    const float* g1  = (const float*)d_in[4];
    const float* be1 = (const float*)d_in[5];
    const float* m1  = (const float*)d_in[6];
    const float* v1  = (const float*)d_in[7];
    const float* W2  = (const float*)d_in[8];
    const float* b2  = (const float*)d_in[9];
    const float* g2  = (const float*)d_in[10];
    const float* be2 = (const float*)d_in[11];
    const float* m2  = (const float*)d_in[12];
    const float* v2  = (const float*)d_in[13];
    const float* fcW = (const float*)d_in[14];
    const float* fcb = (const float*)d_in[15];
    float* out = (float*)d_out;

    const int NB = (NN + 1023) / 1024;       // 98
    const int NTILES = (NN + 127) / 128;     // 782

    // CSR build (counting sort by dst); g_cnt==0 invariant maintained by k_scan3
    k_hist<<<(NE + 255) / 256, 256>>>(col);
    k_scan1<<<NB, 1024>>>();
    k_scan2<<<1, 128>>>();
    k_scan3<<<NB, 1024>>>();
    k_scatter<<<(NE + 255) / 256, 256>>>(row, col);

    // layer 1
    mma_gemm<F1, F0, 0><<<NTILES, 256>>>(x, W1);
    k_agg1<<<(NN * 32 + 255) / 256, 256>>>(b1, m1, v1, g1, be1);

    // layer 2 + fused final linear
    mma_gemm<F2, F1, 1><<<NTILES, 256>>>(nullptr, W2);
    k_agg2_final<<<(NN * 32 + 255) / 256, 256>>>(b2, m2, v2, g2, be2, fcW, fcb, out);
}

// round 9
// speedup vs baseline: 2.5285x; 1.2683x over previous
#include <cuda_runtime.h>
#include <cuda_fp16.h>
#include <cstdint>

#define NN 100000
#define NE 1600000
#define F0 256
#define F1 128
#define F2 64
#define EPSV 1e-5f

// ---------------- scratch (device globals; no allocations allowed) ----------------
__device__ __align__(16) __half2 g_h1s[NN * F1 / 2];  // fp16 messages: (x@W1)*dinv
__device__ __align__(16) float   g_hbn1[NN * F1];     // BN+ReLU(agg1), fp32
__device__ __align__(16) __half2 g_h2s[NN * F2 / 2];  // fp16 messages: (hbn1@W2)*dinv
__device__ float g_dinv[NN];
__device__ int   g_cnt [NN];     // zero at load; re-zeroed by k_scan3 each call
__device__ int   g_ptr [NN + 1];
__device__ int   g_cursor[NN];
__device__ int   g_srcs[NE];
__device__ int   g_bsum[128];

// ---------------- CSR build ----------------
__global__ void k_hist(const int* __restrict__ col) {
    int i = blockIdx.x * blockDim.x + threadIdx.x;   // NE/2 threads
    if (i < NE / 2) {
        int2 c = reinterpret_cast<const int2*>(col)[i];
        atomicAdd(&g_cnt[c.x], 1);
        atomicAdd(&g_cnt[c.y], 1);
    }
}

// pass 1: block-local exclusive scan + block sums + dinv
__global__ void k_scan1() {
    __shared__ int sh[1024];
    int b = blockIdx.x, t = threadIdx.x;
    int i = b * 1024 + t;
    int c = (i < NN) ? g_cnt[i] : 0;
    sh[t] = c;
    __syncthreads();
    for (int off = 1; off < 1024; off <<= 1) {
        int v = (t >= off) ? sh[t - off] : 0;
        __syncthreads();
        sh[t] += v;
        __syncthreads();
    }
    if (i < NN) {
        g_ptr[i] = sh[t] - c;
        g_dinv[i] = rsqrtf((float)(c + 1));
    }
    if (t == 1023) g_bsum[b] = sh[1023];
}

// pass 2: exclusive scan of block sums
__global__ void k_scan2() {
    __shared__ int sh[128];
    const int NB = (NN + 1023) / 1024;  // 98
    int t = threadIdx.x;
    int v = (t < NB) ? g_bsum[t] : 0;
    sh[t] = v;
    __syncthreads();
    for (int off = 1; off < 128; off <<= 1) {
        int u = (t >= off) ? sh[t - off] : 0;
        __syncthreads();
        sh[t] += u;
        __syncthreads();
    }
    if (t < NB) g_bsum[t] = sh[t] - v;
}

// pass 3: add block offsets, init cursors, re-zero g_cnt
__global__ void k_scan3() {
    int b = blockIdx.x, t = threadIdx.x;
    int i = b * 1024 + t;
    if (i < NN) {
        int p = g_ptr[i] + g_bsum[b];
        g_ptr[i] = p;
        g_cursor[i] = p;
        g_cnt[i] = 0;
    }
    if (i == 0) g_ptr[NN] = NE;
}

__global__ void k_scatter(const int* __restrict__ row, const int* __restrict__ col) {
    int i = blockIdx.x * blockDim.x + threadIdx.x;   // NE/2 threads
    if (i < NE / 2) {
        int2 r = reinterpret_cast<const int2*>(row)[i];
        int2 c = reinterpret_cast<const int2*>(col)[i];
        int p0 = atomicAdd(&g_cursor[c.x], 1);
        int p1 = atomicAdd(&g_cursor[c.y], 1);
        g_srcs[p0] = r.x;
        g_srcs[p1] = r.y;
    }
}

// ================= fp16-split mma.sync helpers (baseline PTX, sm_80+) ==========
__device__ __forceinline__ uint32_t smem_u32(const void* p) {
    uint32_t a;
    asm("{ .reg .u64 t; cvta.to.shared.u64 t, %1; cvt.u32.u64 %0, t; }" : "=r"(a) : "l"(p));
    return a;
}

__device__ __forceinline__ void cp16(uint32_t dst, const void* src, bool pred) {
    int sz = pred ? 16 : 0;
    asm volatile("cp.async.cg.shared.global [%0], [%1], 16, %2;"
                 :: "r"(dst), "l"(src), "r"(sz));
}
#define CP_COMMIT() asm volatile("cp.async.commit_group;")
#define CP_WAIT0()  asm volatile("cp.async.wait_group 0;")

__device__ __forceinline__ void split_h2(float x, float y, uint32_t& hi, uint32_t& lo) {
    __half hx = __float2half_rn(x), hy = __float2half_rn(y);
    __half lx = __float2half_rn(x - __half2float(hx));
    __half ly = __float2half_rn(y - __half2float(hy));
    __half2 h = __halves2half2(hx, hy), l = __halves2half2(lx, ly);
    hi = *reinterpret_cast<uint32_t*>(&h);
    lo = *reinterpret_cast<uint32_t*>(&l);
}

__device__ __forceinline__ void mma16816(float* c, const uint32_t* a, const uint32_t* b) {
    asm volatile(
        "mma.sync.aligned.m16n8k16.row.col.f32.f16.f16.f32 "
        "{%0,%1,%2,%3}, {%4,%5,%6,%7}, {%8,%9}, {%0,%1,%2,%3};"
        : "+f"(c[0]), "+f"(c[1]), "+f"(c[2]), "+f"(c[3])
        : "r"(a[0]), "r"(a[1]), "r"(a[2]), "r"(a[3]), "r"(b[0]), "r"(b[1]));
}

// ========= fp16-split tensor GEMM, cp.async double-buffered, fp16 epilogue ======
// Chalf[M,NT] = half( (A[M,KK] @ B[KK,NT]) * dinv[row] )
// WHICH==0: A=arg(x), C=g_h1s ; WHICH==1: A=g_hbn1, C=g_h2s
// CTA 128 x NT; 8 warps 4(m) x 2(n); warp tile 32 x NT/2; BK=16 (one k16 MMA set).
template <int NT, int KK, int WHICH>
__global__ void __launch_bounds__(256)
mma_gemm(const float* __restrict__ Aarg, const float* __restrict__ Bmat) {
    const float* __restrict__ A = (WHICH == 0) ? Aarg : g_hbn1;
    __half2* __restrict__ C = (WHICH == 0) ? g_h1s : g_h2s;

    constexpr int BK = 16;
    constexpr int SA = 20;            // A smem stride (floats)
    constexpr int SB = NT + 4;        // B smem stride (floats)
    constexpr int WN = NT / 2;
    constexpr int MSUB = 2;
    constexpr int NSUB = WN / 8;      // 8 (NT=128) or 4 (NT=64)
    constexpr int NSTAGE = KK / BK;   // 16 or 8

    __shared__ float As[2][128 * SA];
    __shared__ float Bs[2][BK * SB];

    const int tid = threadIdx.x, wid = tid >> 5, lane = tid & 31;
    const int g = lane >> 2, t = lane & 3;
    const int warp_m = wid & 3, warp_n = wid >> 2;
    const int rowBase = blockIdx.x * 128;

    const uint32_t sAs[2] = { smem_u32(As[0]), smem_u32(As[1]) };
    const uint32_t sBs[2] = { smem_u32(Bs[0]), smem_u32(Bs[1]) };

    float acc[MSUB][NSUB][4];
#pragma unroll
    for (int i = 0; i < MSUB; i++)
#pragma unroll
        for (int j = 0; j < NSUB; j++)
#pragma unroll
            for (int q = 0; q < 4; q++) acc[i][j][q] = 0.f;

    // stage loader: raw fp32 tiles via cp.async (src clamped in-bounds when masked)
    auto load_stage = [&](int s, int buf) {
        int kt = s * BK;
        // A: 128 x 16 = 512 float4
#pragma unroll
        for (int it = 0; it < 2; it++) {
            int idx = tid + it * 256;
            int r = idx >> 2, v = idx & 3;
            int gr = rowBase + r;
            bool ok = gr < NN;
            int gsafe = ok ? gr : 0;   // address stays in-bounds; sz=0 discards
            cp16(sAs[buf] + (r * SA + v * 4) * 4,
                 &A[(size_t)gsafe * KK + kt + v * 4], ok);
        }
        // B: 16 x NT float4s
#pragma unroll
        for (int i = tid; i < BK * NT / 4; i += 256) {
            int r = i / (NT / 4), v = i % (NT / 4);
            cp16(sBs[buf] + (r * SB + v * 4) * 4,
                 &Bmat[(size_t)(kt + r) * NT + v * 4], true);
        }
        CP_COMMIT();
    };

    load_stage(0, 0);
    for (int s = 0; s < NSTAGE; s++) {
        int b = s & 1;
        CP_WAIT0();
        __syncthreads();
        if (s + 1 < NSTAGE) load_stage(s + 1, b ^ 1);

        const float* as = As[b];
        const float* bs = Bs[b];
        // B fragments (split in registers)
        uint32_t bh[NSUB][2], bl[NSUB][2];
#pragma unroll
        for (int sn = 0; sn < NSUB; sn++) {
            int col = warp_n * WN + sn * 8 + g;
            float p0 = bs[(2 * t) * SB + col];
            float p1 = bs[(2 * t + 1) * SB + col];
            float p2 = bs[(2 * t + 8) * SB + col];
            float p3 = bs[(2 * t + 9) * SB + col];
            split_h2(p0, p1, bh[sn][0], bl[sn][0]);
            split_h2(p2, p3, bh[sn][1], bl[sn][1]);
        }
#pragma unroll
        for (int sm = 0; sm < MSUB; sm++) {
            int r0 = (warp_m * 32 + sm * 16 + g) * SA;
            int r1 = r0 + 8 * SA;
            float x0 = as[r0 + 2 * t],     x1 = as[r0 + 2 * t + 1];
            float x2 = as[r1 + 2 * t],     x3 = as[r1 + 2 * t + 1];
            float x4 = as[r0 + 2 * t + 8], x5 = as[r0 + 2 * t + 9];
            float x6 = as[r1 + 2 * t + 8], x7 = as[r1 + 2 * t + 9];
            uint32_t ah[4], al[4];
            split_h2(x0, x1, ah[0], al[0]);
            split_h2(x2, x3, ah[1], al[1]);
            split_h2(x4, x5, ah[2], al[2]);
            split_h2(x6, x7, ah[3], al[3]);
#pragma unroll
            for (int sn = 0; sn < NSUB; sn++) {
                mma16816(acc[sm][sn], ah, bh[sn]);   // hi*hi
                mma16816(acc[sm][sn], ah, bl[sn]);   // hi*lo
                mma16816(acc[sm][sn], al, bh[sn]);   // lo*hi
            }
        }
        __syncthreads();
    }

    // ---- epilogue: scale by dinv[row], convert fp16, store half2 ----
#pragma unroll
    for (int sm = 0; sm < MSUB; sm++) {
        int gr0 = rowBase + warp_m * 32 + sm * 16 + g;
        int gr1 = gr0 + 8;
        float dv0 = (gr0 < NN) ? g_dinv[gr0] : 0.f;
        float dv1 = (gr1 < NN) ? g_dinv[gr1] : 0.f;
#pragma unroll
        for (int sn = 0; sn < NSUB; sn++) {
            int col = warp_n * WN + sn * 8 + t * 2;
            if (gr0 < NN)
                C[((size_t)gr0 * NT + col) >> 1] =
                    __floats2half2_rn(acc[sm][sn][0] * dv0, acc[sm][sn][1] * dv0);
            if (gr1 < NN)
                C[((size_t)gr1 * NT + col) >> 1] =
                    __floats2half2_rn(acc[sm][sn][2] * dv1, acc[sm][sn][3] * dv1);
        }
    }
}

// ---------------- fused aggregation + bias + BN + ReLU ----------------
__device__ __forceinline__ float bnrelu(float x, float b, float m, float v, float g, float be) {
    float t = (x + b - m) * rsqrtf(v + EPSV) * g + be;
    return t > 0.f ? t : 0.f;
}

__device__ __forceinline__ float4 h2x2_to_f4(uint2 u) {
    float2 p0 = __half22float2(*reinterpret_cast<__half2*>(&u.x));
    float2 p1 = __half22float2(*reinterpret_cast<__half2*>(&u.y));
    return make_float4(p0.x, p0.y, p1.x, p1.y);
}

// layer 1: 128 fp16 features -> warp-per-node, 4 feats (8B) per lane
__global__ void k_agg1(const float* __restrict__ pb, const float* __restrict__ pm,
                       const float* __restrict__ pv, const float* __restrict__ pg,
                       const float* __restrict__ pbe) {
    int gw = (blockIdx.x * blockDim.x + threadIdx.x) >> 5;
    int lane = threadIdx.x & 31;
    if (gw >= NN) return;
    const uint2* __restrict__ h = reinterpret_cast<const uint2*>(g_h1s);
    int s = g_ptr[gw], e = g_ptr[gw + 1];
    float4 acc = h2x2_to_f4(__ldg(&h[(size_t)gw * 32 + lane]));  // self-loop
    int i = s;
    for (; i + 3 < e; i += 4) {
        int r0 = g_srcs[i], r1 = g_srcs[i + 1], r2 = g_srcs[i + 2], r3 = g_srcs[i + 3];
        float4 a = h2x2_to_f4(__ldg(&h[(size_t)r0 * 32 + lane]));
        float4 b = h2x2_to_f4(__ldg(&h[(size_t)r1 * 32 + lane]));
        float4 c = h2x2_to_f4(__ldg(&h[(size_t)r2 * 32 + lane]));
        float4 d = h2x2_to_f4(__ldg(&h[(size_t)r3 * 32 + lane]));
        acc.x += a.x + b.x + c.x + d.x;
        acc.y += a.y + b.y + c.y + d.y;
        acc.z += a.z + b.z + c.z + d.z;
        acc.w += a.w + b.w + c.w + d.w;
    }
    for (; i < e; i++) {
        float4 a = h2x2_to_f4(__ldg(&h[(size_t)g_srcs[i] * 32 + lane]));
        acc.x += a.x; acc.y += a.y; acc.z += a.z; acc.w += a.w;
    }
    float dv = g_dinv[gw];
    acc.x *= dv; acc.y *= dv; acc.z *= dv; acc.w *= dv;
    float4 B = reinterpret_cast<const float4*>(pb)[lane];
    float4 M = reinterpret_cast<const float4*>(pm)[lane];
    float4 V = reinterpret_cast<const float4*>(pv)[lane];
    float4 G = reinterpret_cast<const float4*>(pg)[lane];
    float4 E = reinterpret_cast<const float4*>(pbe)[lane];
    float4 o;
    o.x = bnrelu(acc.x, B.x, M.x, V.x, G.x, E.x);
    o.y = bnrelu(acc.y, B.y, M.y, V.y, G.y, E.y);
    o.z = bnrelu(acc.z, B.z, M.z, V.z, G.z, E.z);
    o.w = bnrelu(acc.w, B.w, M.w, V.w, G.w, E.w);
    reinterpret_cast<float4*>(g_hbn1)[(size_t)gw * 32 + lane] = o;
}

// layer 2: 64 fp16 features, 2 feats (4B) per lane; fused final 64->2 linear
__global__ void k_agg2_final(const float* __restrict__ pb, const float* __restrict__ pm,
                             const float* __restrict__ pv, const float* __restrict__ pg,
                             const float* __restrict__ pbe,
                             const float* __restrict__ fcW, const float* __restrict__ fcb,
                             float* __restrict__ out) {
    int gw = (blockIdx.x * blockDim.x + threadIdx.x) >> 5;
    int lane = threadIdx.x & 31;
    if (gw >= NN) return;
    const __half2* __restrict__ h = reinterpret_cast<const __half2*>(g_h2s);
    int s = g_ptr[gw], e = g_ptr[gw + 1];
    float2 acc = __half22float2(__ldg(&h[(size_t)gw * 32 + lane]));  // self-loop
    int i = s;
    for (; i + 3 < e; i += 4) {
        int r0 = g_srcs[i], r1 = g_srcs[i + 1], r2 = g_srcs[i + 2], r3 = g_srcs[i + 3];
        float2 a = __half22float2(__ldg(&h[(size_t)r0 * 32 + lane]));
        float2 b = __half22float2(__ldg(&h[(size_t)r1 * 32 + lane]));
        float2 c = __half22float2(__ldg(&h[(size_t)r2 * 32 + lane]));
        float2 d = __half22float2(__ldg(&h[(size_t)r3 * 32 + lane]));
        acc.x += a.x + b.x + c.x + d.x;
        acc.y += a.y + b.y + c.y + d.y;
    }
    for (; i < e; i++) {
        float2 a = __half22float2(__ldg(&h[(size_t)g_srcs[i] * 32 + lane]));
        acc.x += a.x; acc.y += a.y;
    }
    float dv = g_dinv[gw];
    acc.x *= dv; acc.y *= dv;
    float2 B = reinterpret_cast<const float2*>(pb)[lane];
    float2 M = reinterpret_cast<const float2*>(pm)[lane];
    float2 V = reinterpret_cast<const float2*>(pv)[lane];
    float2 G = reinterpret_cast<const float2*>(pg)[lane];
    float2 E = reinterpret_cast<const float2*>(pbe)[lane];
    float2 o;
    o.x = bnrelu(acc.x, B.x, M.x, V.x, G.x, E.x);
    o.y = bnrelu(acc.y, B.y, M.y, V.y, G.y, E.y);
    float4 w = reinterpret_cast<const float4*>(fcW)[lane];
    float a0 = o.x * w.x + o.y * w.z;
    float a1 = o.x * w.y + o.y * w.w;
#pragma unroll
    for (int off = 16; off; off >>= 1) {
        a0 += __shfl_down_sync(0xffffffffu, a0, off);
        a1 += __shfl_down_sync(0xffffffffu, a1, off);
    }
    if (lane == 0) {
        out[(size_t)gw * 2 + 0] = a0 + fcb[0];
        out[(size_t)gw * 2 + 1] = a1 + fcb[1];
    }
}

// ---------------- launch ----------------
extern "C" void kernel_launch(void* const* d_in, const int* in_sizes, int n_in,
                              void* d_out, int out_size) {
    const float* x   = (const float*)d_in[0];
    const int*   ei  = (const int*)d_in[1];
    const int*   row = ei;
    const int*   col = ei + NE;
    const float* W1  = (const float*)d_in[2];
    const float* b1  = (const float*)d_in[3];
    const float* g1  = (const float*)d_in[4];
    const float* be1 = (const float*)d_in[5];
    const float* m1  = (const float*)d_in[6];
    const float* v1  = (const float*)d_in[7];
    const float* W2  = (const float*)d_in[8];
    const float* b2  = (const float*)d_in[9];
    const float* g2  = (const float*)d_in[10];
    const float* be2 = (const float*)d_in[11];
    const float* m2  = (const float*)d_in[12];
    const float* v2  = (const float*)d_in[13];
    const float* fcW = (const float*)d_in[14];
    const float* fcb = (const float*)d_in[15];
    float* out = (float*)d_out;

    const int NB = (NN + 1023) / 1024;       // 98
    const int NTILES = (NN + 127) / 128;     // 782

    // CSR build (counting sort by dst); g_cnt==0 invariant maintained by k_scan3
    k_hist<<<(NE / 2 + 255) / 256, 256>>>(col);
    k_scan1<<<NB, 1024>>>();
    k_scan2<<<1, 128>>>();
    k_scan3<<<NB, 1024>>>();
    k_scatter<<<(NE / 2 + 255) / 256, 256>>>(row, col);

    // layer 1
    mma_gemm<F1, F0, 0><<<NTILES, 256>>>(x, W1);
    k_agg1<<<(NN * 32 + 255) / 256, 256>>>(b1, m1, v1, g1, be1);

    // layer 2 + fused final linear
    mma_gemm<F2, F1, 1><<<NTILES, 256>>>(nullptr, W2);
    k_agg2_final<<<(NN * 32 + 255) / 256, 256>>>(b2, m2, v2, g2, be2, fcW, fcb, out);
}

// round 10
// speedup vs baseline: 2.7526x; 1.0886x over previous
#include <cuda_runtime.h>
#include <cuda_fp16.h>
#include <cstdint>

#define NN 100000
#define NE 1600000
#define F0 256
#define F1 128
#define F2 64
#define EPSV 1e-5f
#define CSRB 64   // blocks running the CSR chain inside the fused kernel

// ---------------- scratch (device globals; no allocations allowed) ----------------
__device__ __align__(16) __half2 g_h1s [NN * F1 / 2];  // fp16 messages: x@W1 (no dinv)
__device__ __align__(16) __half2 g_hbn1[NN * F1 / 2];  // fp16 BN+ReLU(agg1)
__device__ __align__(16) __half2 g_h2s [NN * F2 / 2];  // fp16 messages: (hbn1@W2)*dinv
__device__ float g_dinv[NN];
__device__ int   g_cnt [NN];     // zero at load; re-zeroed inside fused scan
__device__ int   g_ptr [NN + 1];
__device__ int   g_cursor[NN];
__device__ int   g_srcs[NE];
__device__ int   g_bsum[CSRB];
__device__ unsigned g_barrier[4];

// ---------------- helpers ----------------
__device__ __forceinline__ uint32_t smem_u32(const void* p) {
    uint32_t a;
    asm("{ .reg .u64 t; cvta.to.shared.u64 t, %1; cvt.u32.u64 %0, t; }" : "=r"(a) : "l"(p));
    return a;
}
__device__ __forceinline__ void cp16(uint32_t dst, const void* src, bool pred) {
    int sz = pred ? 16 : 0;
    asm volatile("cp.async.cg.shared.global [%0], [%1], 16, %2;"
                 :: "r"(dst), "l"(src), "r"(sz));
}
#define CP_COMMIT() asm volatile("cp.async.commit_group;")
#define CP_WAIT0()  asm volatile("cp.async.wait_group 0;")

__device__ __forceinline__ void split_h2(float x, float y, uint32_t& hi, uint32_t& lo) {
    __half hx = __float2half_rn(x), hy = __float2half_rn(y);
    __half lx = __float2half_rn(x - __half2float(hx));
    __half ly = __float2half_rn(y - __half2float(hy));
    __half2 h = __halves2half2(hx, hy), l = __halves2half2(lx, ly);
    hi = *reinterpret_cast<uint32_t*>(&h);
    lo = *reinterpret_cast<uint32_t*>(&l);
}
__device__ __forceinline__ void mma16816(float* c, const uint32_t* a, const uint32_t* b) {
    asm volatile(
        "mma.sync.aligned.m16n8k16.row.col.f32.f16.f16.f32 "
        "{%0,%1,%2,%3}, {%4,%5,%6,%7}, {%8,%9}, {%0,%1,%2,%3};"
        : "+f"(c[0]), "+f"(c[1]), "+f"(c[2]), "+f"(c[3])
        : "r"(a[0]), "r"(a[1]), "r"(a[2]), "r"(a[3]), "r"(b[0]), "r"(b[1]));
}

// bounded inter-block barrier among the CSRB CSR blocks (never hangs)
__device__ __forceinline__ void csr_barrier(int id) {
    __syncthreads();
    if (threadIdx.x == 0) {
        __threadfence();
        atomicAdd(&g_barrier[id], 1u);
        int it = 0;
        while (atomicAdd(&g_barrier[id], 0u) < (unsigned)CSRB && ++it < (1 << 18)) {}
        __threadfence();
    }
    __syncthreads();
}

// reset barrier counters before each fused launch (clean for graph replays)
__global__ void k_reset() {
    if (threadIdx.x < 4) g_barrier[threadIdx.x] = 0;
}

// ================= fused kernel: CSR chain (blocks 0..63)  ||  gemm1 (rest) =====
__global__ void __launch_bounds__(256)
k_fused1(const float* __restrict__ x, const float* __restrict__ W1,
         const int* __restrict__ row, const int* __restrict__ col) {
    // gemm1 smem (branch-local use; allocated once per block)
    __shared__ float As[2][128 * 20];
    __shared__ float Bs[2][16 * 132];
    __shared__ int   s_scan[256];

    const int tid = threadIdx.x;

    if (blockIdx.x < CSRB) {
        // ======================= CSR chain =======================
        const int b = blockIdx.x;
        // --- hist ---
        for (int i = b * 256 + tid; i < NE / 2; i += CSRB * 256) {
            int2 c = reinterpret_cast<const int2*>(col)[i];
            atomicAdd(&g_cnt[c.x], 1);
            atomicAdd(&g_cnt[c.y], 1);
        }
        csr_barrier(0);
        // --- scan: 7 elems per thread, block scan, cross-block scan ---
        const int T = 7;                     // 64*256*7 = 114688 >= NN
        int start = (b * 256 + tid) * T;
        int cv[T];
        int lsum = 0;
#pragma unroll
        for (int j = 0; j < T; j++) {
            int idx = start + j;
            int c = (idx < NN) ? g_cnt[idx] : 0;
            cv[j] = c;
            lsum += c;
        }
        s_scan[tid] = lsum;
        __syncthreads();
        for (int off = 1; off < 256; off <<= 1) {
            int v = (tid >= off) ? s_scan[tid - off] : 0;
            __syncthreads();
            s_scan[tid] += v;
            __syncthreads();
        }
        int excl = s_scan[tid] - lsum;
        if (tid == 255) g_bsum[b] = s_scan[255];
        csr_barrier(1);
        if (b == 0) {
            int v = (tid < CSRB) ? g_bsum[tid] : 0;
            s_scan[tid] = v;
            __syncthreads();
            for (int off = 1; off < 256; off <<= 1) {
                int u = (tid >= off) ? s_scan[tid - off] : 0;
                __syncthreads();
                s_scan[tid] += u;
                __syncthreads();
            }
            if (tid < CSRB) g_bsum[tid] = s_scan[tid] - v;  // exclusive
        }
        csr_barrier(2);
        int run = g_bsum[b] + excl;
#pragma unroll
        for (int j = 0; j < T; j++) {
            int idx = start + j;
            if (idx < NN) {
                g_ptr[idx] = run;
                g_cursor[idx] = run;
                g_dinv[idx] = rsqrtf((float)(cv[j] + 1));
                g_cnt[idx] = 0;             // maintain zero invariant
                run += cv[j];
            }
        }
        if (b == 0 && tid == 0) g_ptr[NN] = NE;
        csr_barrier(3);
        // --- scatter ---
        for (int i = b * 256 + tid; i < NE / 2; i += CSRB * 256) {
            int2 r = reinterpret_cast<const int2*>(row)[i];
            int2 c = reinterpret_cast<const int2*>(col)[i];
            g_srcs[atomicAdd(&g_cursor[c.x], 1)] = r.x;
            g_srcs[atomicAdd(&g_cursor[c.y], 1)] = r.y;
        }
    } else {
        // ================== gemm1: h1 = x @ W1 (fp16 out, NO dinv) ==================
        constexpr int NT = F1, KK = F0, BK = 16;
        constexpr int SA = 20, SB = NT + 4;     // 132
        constexpr int WN = NT / 2;              // 64
        constexpr int MSUB = 2, NSUB = WN / 8;  // 8
        constexpr int NSTAGE = KK / BK;         // 16

        const int wid = tid >> 5, lane = tid & 31;
        const int g = lane >> 2, t = lane & 3;
        const int warp_m = wid & 3, warp_n = wid >> 2;
        const int rowBase = (blockIdx.x - CSRB) * 128;

        const uint32_t sAs[2] = { smem_u32(As[0]), smem_u32(As[1]) };
        const uint32_t sBs[2] = { smem_u32(Bs[0]), smem_u32(Bs[1]) };

        float acc[MSUB][NSUB][4];
#pragma unroll
        for (int i = 0; i < MSUB; i++)
#pragma unroll
            for (int j = 0; j < NSUB; j++)
#pragma unroll
                for (int q = 0; q < 4; q++) acc[i][j][q] = 0.f;

        auto load_stage = [&](int s, int buf) {
            int kt = s * BK;
#pragma unroll
            for (int it = 0; it < 2; it++) {
                int idx = tid + it * 256;
                int r = idx >> 2, v = idx & 3;
                int gr = rowBase + r;
                bool ok = gr < NN;
                int gs = ok ? gr : 0;
                cp16(sAs[buf] + (r * SA + v * 4) * 4, &x[(size_t)gs * KK + kt + v * 4], ok);
            }
#pragma unroll
            for (int i = tid; i < BK * NT / 4; i += 256) {
                int r = i / (NT / 4), v = i % (NT / 4);
                cp16(sBs[buf] + (r * SB + v * 4) * 4, &W1[(size_t)(kt + r) * NT + v * 4], true);
            }
            CP_COMMIT();
        };

        load_stage(0, 0);
        for (int s = 0; s < NSTAGE; s++) {
            int b = s & 1;
            CP_WAIT0();
            __syncthreads();
            if (s + 1 < NSTAGE) load_stage(s + 1, b ^ 1);

            const float* as = As[b];
            const float* bs = Bs[b];
            uint32_t bh[NSUB][2], bl[NSUB][2];
#pragma unroll
            for (int sn = 0; sn < NSUB; sn++) {
                int cc = warp_n * WN + sn * 8 + g;
                split_h2(bs[(2 * t) * SB + cc], bs[(2 * t + 1) * SB + cc], bh[sn][0], bl[sn][0]);
                split_h2(bs[(2 * t + 8) * SB + cc], bs[(2 * t + 9) * SB + cc], bh[sn][1], bl[sn][1]);
            }
#pragma unroll
            for (int sm = 0; sm < MSUB; sm++) {
                int r0 = (warp_m * 32 + sm * 16 + g) * SA;
                int r1 = r0 + 8 * SA;
                uint32_t ah[4], al[4];
                split_h2(as[r0 + 2 * t], as[r0 + 2 * t + 1], ah[0], al[0]);
                split_h2(as[r1 + 2 * t], as[r1 + 2 * t + 1], ah[1], al[1]);
                split_h2(as[r0 + 2 * t + 8], as[r0 + 2 * t + 9], ah[2], al[2]);
                split_h2(as[r1 + 2 * t + 8], as[r1 + 2 * t + 9], ah[3], al[3]);
#pragma unroll
                for (int sn = 0; sn < NSUB; sn++) {
                    mma16816(acc[sm][sn], ah, bh[sn]);
                    mma16816(acc[sm][sn], ah, bl[sn]);
                    mma16816(acc[sm][sn], al, bh[sn]);
                }
            }
            __syncthreads();
        }
        // epilogue: plain fp16 store (dinv applied later in agg1)
#pragma unroll
        for (int sm = 0; sm < MSUB; sm++) {
            int gr0 = rowBase + warp_m * 32 + sm * 16 + g;
            int gr1 = gr0 + 8;
#pragma unroll
            for (int sn = 0; sn < NSUB; sn++) {
                int cc = warp_n * WN + sn * 8 + t * 2;
                if (gr0 < NN)
                    g_h1s[((size_t)gr0 * NT + cc) >> 1] =
                        __floats2half2_rn(acc[sm][sn][0], acc[sm][sn][1]);
                if (gr1 < NN)
                    g_h1s[((size_t)gr1 * NT + cc) >> 1] =
                        __floats2half2_rn(acc[sm][sn][2], acc[sm][sn][3]);
            }
        }
    }
}

// ================= gemm2: h2s = (hbn1_fp16 @ W2) * dinv, fp16 out ===============
// A is exact fp16 -> only 2 MMA terms (A*Bhi + A*Blo).
__global__ void __launch_bounds__(256)
mma_gemm2(const float* __restrict__ Bmat) {
    constexpr int NT = F2, KK = F1, BK = 16;
    constexpr int SA2 = 12;                 // u32 (half2) per A row, padded
    constexpr int SB = NT + 4;              // 68
    constexpr int WN = NT / 2;              // 32
    constexpr int MSUB = 2, NSUB = WN / 8;  // 4
    constexpr int NSTAGE = KK / BK;         // 8

    __shared__ uint32_t As2[2][128 * SA2];
    __shared__ float    Bs[2][BK * SB];

    const int tid = threadIdx.x, wid = tid >> 5, lane = tid & 31;
    const int g = lane >> 2, t = lane & 3;
    const int warp_m = wid & 3, warp_n = wid >> 2;
    const int rowBase = blockIdx.x * 128;

    const uint32_t sAs[2] = { smem_u32(As2[0]), smem_u32(As2[1]) };
    const uint32_t sBs[2] = { smem_u32(Bs[0]), smem_u32(Bs[1]) };
    const __half2* __restrict__ Ah = g_hbn1;

    float acc[MSUB][NSUB][4];
#pragma unroll
    for (int i = 0; i < MSUB; i++)
#pragma unroll
        for (int j = 0; j < NSUB; j++)
#pragma unroll
            for (int q = 0; q < 4; q++) acc[i][j][q] = 0.f;

    auto load_stage = [&](int s, int buf) {
        int kt = s * BK;
        // A: 128 rows x 16 halfs = 2 x 16B chunks per row; 256 chunks == 256 threads
        {
            int r = tid >> 1, v = tid & 1;
            int gr = rowBase + r;
            bool ok = gr < NN;
            int gs = ok ? gr : 0;
            cp16(sAs[buf] + (r * SA2 + v * 4) * 4,
                 &Ah[(size_t)gs * (KK / 2) + kt / 2 + v * 4], ok);
        }
        // B: 16 x 64 floats = 256 float4 == 256 threads
        {
            int r = tid / (NT / 4), v = tid % (NT / 4);
            cp16(sBs[buf] + (r * SB + v * 4) * 4, &Bmat[(size_t)(kt + r) * NT + v * 4], true);
        }
        CP_COMMIT();
    };

    load_stage(0, 0);
    for (int s = 0; s < NSTAGE; s++) {
        int b = s & 1;
        CP_WAIT0();
        __syncthreads();
        if (s + 1 < NSTAGE) load_stage(s + 1, b ^ 1);

        const uint32_t* as = As2[b];
        const float* bs = Bs[b];
        uint32_t bh[NSUB][2], bl[NSUB][2];
#pragma unroll
        for (int sn = 0; sn < NSUB; sn++) {
            int cc = warp_n * WN + sn * 8 + g;
            split_h2(bs[(2 * t) * SB + cc], bs[(2 * t + 1) * SB + cc], bh[sn][0], bl[sn][0]);
            split_h2(bs[(2 * t + 8) * SB + cc], bs[(2 * t + 9) * SB + cc], bh[sn][1], bl[sn][1]);
        }
#pragma unroll
        for (int sm = 0; sm < MSUB; sm++) {
            int rg = warp_m * 32 + sm * 16 + g;
            uint32_t ah[4];
            ah[0] = as[rg * SA2 + t];
            ah[1] = as[(rg + 8) * SA2 + t];
            ah[2] = as[rg * SA2 + t + 4];
            ah[3] = as[(rg + 8) * SA2 + t + 4];
#pragma unroll
            for (int sn = 0; sn < NSUB; sn++) {
                mma16816(acc[sm][sn], ah, bh[sn]);
                mma16816(acc[sm][sn], ah, bl[sn]);
            }
        }
        __syncthreads();
    }
    // epilogue: dinv scale, fp16 store
#pragma unroll
    for (int sm = 0; sm < MSUB; sm++) {
        int gr0 = rowBase + warp_m * 32 + sm * 16 + g;
        int gr1 = gr0 + 8;
        float dv0 = (gr0 < NN) ? g_dinv[gr0] : 0.f;
        float dv1 = (gr1 < NN) ? g_dinv[gr1] : 0.f;
#pragma unroll
        for (int sn = 0; sn < NSUB; sn++) {
            int cc = warp_n * WN + sn * 8 + t * 2;
            if (gr0 < NN)
                g_h2s[((size_t)gr0 * NT + cc) >> 1] =
                    __floats2half2_rn(acc[sm][sn][0] * dv0, acc[sm][sn][1] * dv0);
            if (gr1 < NN)
                g_h2s[((size_t)gr1 * NT + cc) >> 1] =
                    __floats2half2_rn(acc[sm][sn][2] * dv1, acc[sm][sn][3] * dv1);
        }
    }
}

// ---------------- fused aggregation + bias + BN + ReLU ----------------
__device__ __forceinline__ float bnrelu(float x, float b, float m, float v, float g, float be) {
    float t = (x + b - m) * rsqrtf(v + EPSV) * g + be;
    return t > 0.f ? t : 0.f;
}
__device__ __forceinline__ float4 h2x2_to_f4(uint2 u) {
    float2 p0 = __half22float2(*reinterpret_cast<__half2*>(&u.x));
    float2 p1 = __half22float2(*reinterpret_cast<__half2*>(&u.y));
    return make_float4(p0.x, p0.y, p1.x, p1.y);
}

// layer 1: msg = h1 (plain); acc = msg[v]*dinv[v] + sum msg[src]*dinv[src]; out=acc*dinv[v]
__global__ void k_agg1(const float* __restrict__ pb, const float* __restrict__ pm,
                       const float* __restrict__ pv, const float* __restrict__ pg,
                       const float* __restrict__ pbe) {
    int gw = (blockIdx.x * blockDim.x + threadIdx.x) >> 5;
    int lane = threadIdx.x & 31;
    if (gw >= NN) return;
    const uint2* __restrict__ h = reinterpret_cast<const uint2*>(g_h1s);
    float dvv = g_dinv[gw];
    int s = g_ptr[gw], e = g_ptr[gw + 1];
    float4 acc = h2x2_to_f4(__ldg(&h[(size_t)gw * 32 + lane]));
    acc.x *= dvv; acc.y *= dvv; acc.z *= dvv; acc.w *= dvv;   // self-loop term
    int i = s;
    for (; i + 3 < e; i += 4) {
        int r0 = g_srcs[i], r1 = g_srcs[i + 1], r2 = g_srcs[i + 2], r3 = g_srcs[i + 3];
        float d0 = __ldg(&g_dinv[r0]), d1 = __ldg(&g_dinv[r1]);
        float d2 = __ldg(&g_dinv[r2]), d3 = __ldg(&g_dinv[r3]);
        float4 a = h2x2_to_f4(__ldg(&h[(size_t)r0 * 32 + lane]));
        float4 b = h2x2_to_f4(__ldg(&h[(size_t)r1 * 32 + lane]));
        float4 c = h2x2_to_f4(__ldg(&h[(size_t)r2 * 32 + lane]));
        float4 d = h2x2_to_f4(__ldg(&h[(size_t)r3 * 32 + lane]));
        acc.x += a.x * d0 + b.x * d1 + c.x * d2 + d.x * d3;
        acc.y += a.y * d0 + b.y * d1 + c.y * d2 + d.y * d3;
        acc.z += a.z * d0 + b.z * d1 + c.z * d2 + d.z * d3;
        acc.w += a.w * d0 + b.w * d1 + c.w * d2 + d.w * d3;
    }
    for (; i < e; i++) {
        int r = g_srcs[i];
        float dr = __ldg(&g_dinv[r]);
        float4 a = h2x2_to_f4(__ldg(&h[(size_t)r * 32 + lane]));
        acc.x += a.x * dr; acc.y += a.y * dr; acc.z += a.z * dr; acc.w += a.w * dr;
    }
    acc.x *= dvv; acc.y *= dvv; acc.z *= dvv; acc.w *= dvv;
    float4 B = reinterpret_cast<const float4*>(pb)[lane];
    float4 M = reinterpret_cast<const float4*>(pm)[lane];
    float4 V = reinterpret_cast<const float4*>(pv)[lane];
    float4 G = reinterpret_cast<const float4*>(pg)[lane];
    float4 E = reinterpret_cast<const float4*>(pbe)[lane];
    float4 o;
    o.x = bnrelu(acc.x, B.x, M.x, V.x, G.x, E.x);
    o.y = bnrelu(acc.y, B.y, M.y, V.y, G.y, E.y);
    o.z = bnrelu(acc.z, B.z, M.z, V.z, G.z, E.z);
    o.w = bnrelu(acc.w, B.w, M.w, V.w, G.w, E.w);
    __half2 p0 = __floats2half2_rn(o.x, o.y);
    __half2 p1 = __floats2half2_rn(o.z, o.w);
    uint2 st;
    st.x = *reinterpret_cast<uint32_t*>(&p0);
    st.y = *reinterpret_cast<uint32_t*>(&p1);
    reinterpret_cast<uint2*>(g_hbn1)[(size_t)gw * 32 + lane] = st;
}

// layer 2 agg + fused final 64->2 linear
__global__ void k_agg2_final(const float* __restrict__ pb, const float* __restrict__ pm,
                             const float* __restrict__ pv, const float* __restrict__ pg,
                             const float* __restrict__ pbe,
                             const float* __restrict__ fcW, const float* __restrict__ fcb,
                             float* __restrict__ out) {
    int gw = (blockIdx.x * blockDim.x + threadIdx.x) >> 5;
    int lane = threadIdx.x & 31;
    if (gw >= NN) return;
    const __half2* __restrict__ h = g_h2s;
    int s = g_ptr[gw], e = g_ptr[gw + 1];
    float2 acc = __half22float2(__ldg(&h[(size_t)gw * 32 + lane]));  // self-loop (dinv folded)
    int i = s;
    for (; i + 3 < e; i += 4) {
        int r0 = g_srcs[i], r1 = g_srcs[i + 1], r2 = g_srcs[i + 2], r3 = g_srcs[i + 3];
        float2 a = __half22float2(__ldg(&h[(size_t)r0 * 32 + lane]));
        float2 b = __half22float2(__ldg(&h[(size_t)r1 * 32 + lane]));
        float2 c = __half22float2(__ldg(&h[(size_t)r2 * 32 + lane]));
        float2 d = __half22float2(__ldg(&h[(size_t)r3 * 32 + lane]));
        acc.x += a.x + b.x + c.x + d.x;
        acc.y += a.y + b.y + c.y + d.y;
    }
    for (; i < e; i++) {
        float2 a = __half22float2(__ldg(&h[(size_t)g_srcs[i] * 32 + lane]));
        acc.x += a.x; acc.y += a.y;
    }
    float dv = g_dinv[gw];
    acc.x *= dv; acc.y *= dv;
    float2 B = reinterpret_cast<const float2*>(pb)[lane];
    float2 M = reinterpret_cast<const float2*>(pm)[lane];
    float2 V = reinterpret_cast<const float2*>(pv)[lane];
    float2 G = reinterpret_cast<const float2*>(pg)[lane];
    float2 E = reinterpret_cast<const float2*>(pbe)[lane];
    float2 o;
    o.x = bnrelu(acc.x, B.x, M.x, V.x, G.x, E.x);
    o.y = bnrelu(acc.y, B.y, M.y, V.y, G.y, E.y);
    float4 w = reinterpret_cast<const float4*>(fcW)[lane];
    float a0 = o.x * w.x + o.y * w.z;
    float a1 = o.x * w.y + o.y * w.w;
#pragma unroll
    for (int off = 16; off; off >>= 1) {
        a0 += __shfl_down_sync(0xffffffffu, a0, off);
        a1 += __shfl_down_sync(0xffffffffu, a1, off);
    }
    if (lane == 0) {
        out[(size_t)gw * 2 + 0] = a0 + fcb[0];
        out[(size_t)gw * 2 + 1] = a1 + fcb[1];
    }
}

// ---------------- launch ----------------
extern "C" void kernel_launch(void* const* d_in, const int* in_sizes, int n_in,
                              void* d_out, int out_size) {
    const float* x   = (const float*)d_in[0];
    const int*   ei  = (const int*)d_in[1];
    const int*   row = ei;
    const int*   col = ei + NE;
    const float* W1  = (const float*)d_in[2];
    const float* b1  = (const float*)d_in[3];
    const float* g1  = (const float*)d_in[4];
    const float* be1 = (const float*)d_in[5];
    const float* m1  = (const float*)d_in[6];
    const float* v1  = (const float*)d_in[7];
    const float* W2  = (const float*)d_in[8];
    const float* b2  = (const float*)d_in[9];
    const float* g2  = (const float*)d_in[10];
    const float* be2 = (const float*)d_in[11];
    const float* m2  = (const float*)d_in[12];
    const float* v2  = (const float*)d_in[13];
    const float* fcW = (const float*)d_in[14];
    const float* fcb = (const float*)d_in[15];
    float* out = (float*)d_out;

    const int NTILES = (NN + 127) / 128;     // 782

    k_reset<<<1, 32>>>();
    // fused: CSR chain (64 blocks) overlapped with gemm1 (782 blocks)
    k_fused1<<<CSRB + NTILES, 256>>>(x, W1, row, col);
    k_agg1<<<(NN * 32 + 255) / 256, 256>>>(b1, m1, v1, g1, be1);
    mma_gemm2<<<NTILES, 256>>>(W2);
    k_agg2_final<<<(NN * 32 + 255) / 256, 256>>>(b2, m2, v2, g2, be2, fcW, fcb, out);
}